// round 2
// baseline (speedup 1.0000x reference)
#include <cuda_runtime.h>
#include <cstdint>

#define HWD 12544        // 112*112
#define TOKS 100352      // 2048 windows * 49
#define QSCALE 0.17677669529663687f   // 32^-0.5

// Scratch (allocation-free contract: __device__ globals)
__device__ float g_q[(size_t)TOKS * 256];
__device__ float g_k[(size_t)TOKS * 256];
__device__ float g_v[(size_t)TOKS * 256];
__device__ float g_at[(size_t)TOKS * 256];   // attention output, TRANSPOSED [c][t]

// ---------------------------------------------------------------------------
// K1: QKV GEMM.  out[t, 0:768] = x_window_gathered[t, :] @ w_qkv + b_qkv
// Tile 128(M) x 128(N) x 32(K), 256 threads, 8x8 register tile.
// Epilogue scatters into g_q/g_k/g_v with layout [win][head][n][d], q scaled.
// ---------------------------------------------------------------------------
__global__ __launch_bounds__(256) void k1_qkv(
    const float* __restrict__ x, const float* __restrict__ w,
    const float* __restrict__ bias)
{
    __shared__ float As[32][128];
    __shared__ float Bs[32][128];
    __shared__ int boff[128];
    const int tid = threadIdx.x;
    const int tx = tid & 15, ty = tid >> 4;
    const int t0 = blockIdx.x * 128;
    const int n0 = blockIdx.y * 128;

    if (tid < 128) {
        int t = t0 + tid;
        int win = t / 49, n = t - win * 49;
        int b = win >> 8, rem = win & 255;
        int h  = (rem >> 4) * 7 + n / 7;
        int wc = (rem & 15) * 7 + n % 7;
        boff[tid] = b * (256 * HWD) + h * 112 + wc;
    }
    float acc[8][8];
    #pragma unroll
    for (int i = 0; i < 8; i++)
        #pragma unroll
        for (int j = 0; j < 8; j++) acc[i][j] = 0.f;
    __syncthreads();

    for (int k0 = 0; k0 < 256; k0 += 32) {
        #pragma unroll
        for (int i = 0; i < 16; i++) {
            int idx = tid + i * 256;        // 0..4095
            int m = idx & 127, k = idx >> 7;
            As[k][m] = __ldg(&x[boff[m] + (k0 + k) * HWD]);
        }
        #pragma unroll
        for (int i = 0; i < 4; i++) {
            int f = tid + i * 256;          // float4 index, 0..1023
            int n4 = f & 31, k = f >> 5;
            *(float4*)&Bs[k][n4 * 4] =
                *(const float4*)&w[(k0 + k) * 768 + n0 + n4 * 4];
        }
        __syncthreads();
        #pragma unroll
        for (int kk = 0; kk < 32; kk++) {
            float a[8], b[8];
            *(float4*)&a[0] = *(float4*)&As[kk][ty * 8];
            *(float4*)&a[4] = *(float4*)&As[kk][ty * 8 + 4];
            *(float4*)&b[0] = *(float4*)&Bs[kk][tx * 8];
            *(float4*)&b[4] = *(float4*)&Bs[kk][tx * 8 + 4];
            #pragma unroll
            for (int i = 0; i < 8; i++)
                #pragma unroll
                for (int j = 0; j < 8; j++)
                    acc[i][j] += a[i] * b[j];
        }
        __syncthreads();
    }

    // Epilogue: col block of 8 is always inside one (which, head) region.
    int col = n0 + tx * 8;
    int which = col >> 8;
    int head  = (col >> 5) & 7;
    int d     = col & 31;
    float bj[8];
    *(float4*)&bj[0] = *(const float4*)&bias[col];
    *(float4*)&bj[4] = *(const float4*)&bias[col + 4];
    float scl = (which == 0) ? QSCALE : 1.f;
    float* dst = (which == 0) ? g_q : (which == 1) ? g_k : g_v;
    #pragma unroll
    for (int i = 0; i < 8; i++) {
        int t = t0 + ty * 8 + i;
        int win = t / 49, n = t - win * 49;
        size_t off = ((size_t)(win * 8 + head) * 49 + n) * 32 + d;
        float v[8];
        #pragma unroll
        for (int j = 0; j < 8; j++) v[j] = (acc[i][j] + bj[j]) * scl;
        *(float4*)&dst[off]     = *(float4*)&v[0];
        *(float4*)&dst[off + 4] = *(float4*)&v[4];
    }
}

// ---------------------------------------------------------------------------
// K2: per-(window,head) attention.  S = q@k^T + rpb_bias ; softmax ; O = P@V
// Writes O into g_at transposed: g_at[(head*32+d)*TOKS + win*49 + n]
// ---------------------------------------------------------------------------
__global__ __launch_bounds__(256) void k2_attn(const float* __restrict__ rpb)
{
    __shared__ float qs[32][56];    // [d][n] transposed
    __shared__ float ks[32][56];
    __shared__ float vs[49][33];    // [m][d]
    __shared__ float Ss[56][51];
    const int tid  = threadIdx.x;
    const int wh   = blockIdx.x;    // win*8 + head
    const int head = wh & 7;
    const int win  = wh >> 3;
    const size_t base = (size_t)wh * 1568;

    for (int idx = tid; idx < 1568; idx += 256) {
        int n = idx >> 5, d = idx & 31;
        qs[d][n] = g_q[base + idx];
        ks[d][n] = g_k[base + idx];
        vs[n][d] = g_v[base + idx];
    }
    __syncthreads();

    // ---- scores: 196 threads, 4x4 tiles over padded 56x56 ----
    if (tid < 196) {
        int tyy = tid / 14, txx = tid - tyy * 14;
        int nb = tyy * 4, mb = txx * 4;
        float s[4][4];
        #pragma unroll
        for (int i = 0; i < 4; i++)
            #pragma unroll
            for (int j = 0; j < 4; j++) s[i][j] = 0.f;
        #pragma unroll
        for (int kk = 0; kk < 32; kk++) {
            float qq[4], kf[4];
            #pragma unroll
            for (int i = 0; i < 4; i++) qq[i] = qs[kk][nb + i];
            #pragma unroll
            for (int j = 0; j < 4; j++) kf[j] = ks[kk][mb + j];
            #pragma unroll
            for (int i = 0; i < 4; i++)
                #pragma unroll
                for (int j = 0; j < 4; j++) s[i][j] += qq[i] * kf[j];
        }
        #pragma unroll
        for (int i = 0; i < 4; i++) {
            int n = nb + i;
            if (n < 49) {
                int in_ = n / 7, jn = n - in_ * 7;
                #pragma unroll
                for (int j = 0; j < 4; j++) {
                    int m = mb + j;
                    if (m < 49) {
                        int im = m / 7, jm = m - im * 7;
                        int ridx = (in_ - im + 6) * 13 + (jn - jm + 6);
                        Ss[n][m] = s[i][j] + rpb[ridx * 8 + head];
                    }
                }
            }
        }
    }
    __syncthreads();

    // ---- softmax: warp per row ----
    {
        int lane = tid & 31, wrp = tid >> 5;
        for (int r = wrp; r < 49; r += 8) {
            float v0 = Ss[r][lane];
            float v1 = (lane < 17) ? Ss[r][lane + 32] : -3.0e38f;
            float mx = fmaxf(v0, v1);
            #pragma unroll
            for (int o = 16; o; o >>= 1)
                mx = fmaxf(mx, __shfl_xor_sync(0xffffffffu, mx, o));
            float e0 = __expf(v0 - mx);
            float e1 = (lane < 17) ? __expf(v1 - mx) : 0.f;
            float sm = e0 + e1;
            #pragma unroll
            for (int o = 16; o; o >>= 1)
                sm += __shfl_xor_sync(0xffffffffu, sm, o);
            float inv = __fdividef(1.f, sm);
            Ss[r][lane] = e0 * inv;
            if (lane < 17) Ss[r][lane + 32] = e1 * inv;
        }
    }
    __syncthreads();

    // ---- O = P@V : 224 threads, 4(n) x 2(d) tiles.  Stage into Os (reuses qs).
    float* Os = &qs[0][0];          // stride 53, 31*53+48 = 1691 < 1792
    if (tid < 224) {
        int tyy = tid >> 4, txx = tid & 15;
        int nb = tyy * 4, db = txx * 2;
        float o[4][2];
        #pragma unroll
        for (int i = 0; i < 4; i++) { o[i][0] = 0.f; o[i][1] = 0.f; }
        for (int m = 0; m < 49; m++) {
            float va = vs[m][db], vb = vs[m][db + 1];
            #pragma unroll
            for (int i = 0; i < 4; i++) {
                float p = Ss[nb + i][m];
                o[i][0] += p * va;
                o[i][1] += p * vb;
            }
        }
        #pragma unroll
        for (int j = 0; j < 2; j++)
            #pragma unroll
            for (int i = 0; i < 4; i++)
                if (nb + i < 49) Os[(db + j) * 53 + nb + i] = o[i][j];
    }
    __syncthreads();

    for (int e = tid; e < 1568; e += 256) {
        int d = e / 49, n = e - d * 49;
        g_at[(size_t)(head * 32 + d) * TOKS + win * 49 + n] = Os[d * 53 + n];
    }
}

// ---------------------------------------------------------------------------
// K3: projection GEMM + window-reverse scatter to NCHW.
// A = g_at transposed [c][t] -> coalesced float4 loads, no smem transpose.
// ---------------------------------------------------------------------------
__global__ __launch_bounds__(256) void k3_proj(
    const float* __restrict__ w, const float* __restrict__ bias,
    float* __restrict__ out)
{
    __shared__ float sm3[8192];     // As [32][128] | Bs [32][128]; reused as stage
    __shared__ int boff[128];
    float* As = sm3;
    float* Bs = sm3 + 4096;
    const int tid = threadIdx.x;
    const int tx = tid & 15, ty = tid >> 4;
    const int t0 = blockIdx.x * 128;
    const int n0 = blockIdx.y * 128;

    if (tid < 128) {
        int t = t0 + tid;
        int win = t / 49, n = t - win * 49;
        int b = win >> 8, rem = win & 255;
        int h  = (rem >> 4) * 7 + n / 7;
        int wc = (rem & 15) * 7 + n % 7;
        boff[tid] = b * (256 * HWD) + h * 112 + wc;
    }
    float acc[8][8];
    #pragma unroll
    for (int i = 0; i < 8; i++)
        #pragma unroll
        for (int j = 0; j < 8; j++) acc[i][j] = 0.f;
    __syncthreads();

    for (int k0 = 0; k0 < 256; k0 += 32) {
        #pragma unroll
        for (int i = 0; i < 4; i++) {
            int f = tid + i * 256;
            int k = f >> 5, m4 = f & 31;
            *(float4*)&As[k * 128 + m4 * 4] =
                *(const float4*)&g_at[(size_t)(k0 + k) * TOKS + t0 + m4 * 4];
        }
        #pragma unroll
        for (int i = 0; i < 4; i++) {
            int f = tid + i * 256;
            int k = f >> 5, n4 = f & 31;
            *(float4*)&Bs[k * 128 + n4 * 4] =
                *(const float4*)&w[(k0 + k) * 256 + n0 + n4 * 4];
        }
        __syncthreads();
        #pragma unroll
        for (int kk = 0; kk < 32; kk++) {
            float a[8], b[8];
            *(float4*)&a[0] = *(float4*)&As[kk * 128 + ty * 8];
            *(float4*)&a[4] = *(float4*)&As[kk * 128 + ty * 8 + 4];
            *(float4*)&b[0] = *(float4*)&Bs[kk * 128 + tx * 8];
            *(float4*)&b[4] = *(float4*)&Bs[kk * 128 + tx * 8 + 4];
            #pragma unroll
            for (int i = 0; i < 8; i++)
                #pragma unroll
                for (int j = 0; j < 8; j++)
                    acc[i][j] += a[i] * b[j];
        }
        __syncthreads();
    }

    float bj[8];
    *(float4*)&bj[0] = *(const float4*)&bias[n0 + tx * 8];
    *(float4*)&bj[4] = *(const float4*)&bias[n0 + tx * 8 + 4];

    // Stage 32 rows at a time through smem, then write with token-contiguous
    // threads (7-contiguous w runs -> good sectors) instead of stride-HWD scatter.
    float* stg = sm3;               // 32*129 = 4128 floats
    for (int rh = 0; rh < 4; rh++) {
        if ((ty >> 2) == rh) {
            int tyl = ty & 3;
            #pragma unroll
            for (int i = 0; i < 8; i++)
                #pragma unroll
                for (int j = 0; j < 8; j++)
                    stg[(tyl * 8 + i) * 129 + tx * 8 + j] = acc[i][j] + bj[j];
        }
        __syncthreads();
        #pragma unroll
        for (int p = 0; p < 16; p++) {
            int e = tid + p * 256;              // 0..4095
            int mloc = e & 31, colj = e >> 5;   // col 0..127
            out[boff[rh * 32 + mloc] + (n0 + colj) * HWD] = stg[mloc * 129 + colj];
        }
        __syncthreads();
    }
}

// ---------------------------------------------------------------------------
extern "C" void kernel_launch(void* const* d_in, const int* in_sizes, int n_in,
                              void* d_out, int out_size)
{
    const float* x      = (const float*)d_in[0];
    const float* w_qkv  = (const float*)d_in[1];
    const float* b_qkv  = (const float*)d_in[2];
    const float* w_proj = (const float*)d_in[3];
    const float* b_proj = (const float*)d_in[4];
    const float* rpb    = (const float*)d_in[5];
    float* out = (float*)d_out;

    k1_qkv<<<dim3(784, 6), 256>>>(x, w_qkv, b_qkv);
    k2_attn<<<16384, 256>>>(rpb);
    k3_proj<<<dim3(784, 2), 256>>>(w_proj, b_proj, out);
}

// round 9
// speedup vs baseline: 2.4372x; 2.4372x over previous
#include <cuda_runtime.h>
#include <cuda_bf16.h>
#include <cstdint>

#define HWD 12544        // 112*112
#define TOKS 100352      // 2048 windows * 49
#define QSCALE 0.17677669529663687f   // 32^-0.5

// ========================= device scratch ===================================
__device__ float g_q[(size_t)TOKS * 256];
__device__ float g_k[(size_t)TOKS * 256];
__device__ float g_v[(size_t)TOKS * 256];
__device__ __nv_bfloat162 g_at_hl[(size_t)TOKS * 256];   // [c][t], (h,l) packed
__device__ __nv_bfloat16 g_wqkvT_h[768 * 256];           // [n][k]
__device__ __nv_bfloat16 g_wqkvT_l[768 * 256];
__device__ __nv_bfloat16 g_wprojT_h[256 * 256];
__device__ __nv_bfloat16 g_wprojT_l[256 * 256];

__device__ __forceinline__ void split_bf16(float v, __nv_bfloat16& h, __nv_bfloat16& l) {
    h = __float2bfloat16(v);
    l = __float2bfloat16(v - __bfloat162float(h));
}

// mma.sync m16n8k16 bf16 (base ISA, sm_80+; compiles for sm_100)
__device__ __forceinline__ void mma16816(
    float* d, const uint32_t* a, const uint32_t* b)
{
    asm volatile(
        "mma.sync.aligned.m16n8k16.row.col.f32.bf16.bf16.f32 "
        "{%0,%1,%2,%3}, {%4,%5,%6,%7}, {%8,%9}, {%0,%1,%2,%3};"
        : "+f"(d[0]), "+f"(d[1]), "+f"(d[2]), "+f"(d[3])
        : "r"(a[0]), "r"(a[1]), "r"(a[2]), "r"(a[3]), "r"(b[0]), "r"(b[1]));
}

#define KPAD 40   // bf16 per smem row (32 data + 8 pad) -> 80B stride, conflict-free

// ========================= k0: weight transpose + split =====================
__global__ void k0_wqkv(const float* __restrict__ w) {
    int idx = blockIdx.x * 256 + threadIdx.x;     // < 196608
    int k = idx / 768, n = idx % 768;
    __nv_bfloat16 h, l; split_bf16(w[idx], h, l);
    g_wqkvT_h[n * 256 + k] = h;
    g_wqkvT_l[n * 256 + k] = l;
}
__global__ void k0_wproj(const float* __restrict__ w) {
    int idx = blockIdx.x * 256 + threadIdx.x;     // < 65536
    int k = idx >> 8, n = idx & 255;
    __nv_bfloat16 h, l; split_bf16(w[idx], h, l);
    g_wprojT_h[n * 256 + k] = h;
    g_wprojT_l[n * 256 + k] = l;
}

// ========================= k1: QKV GEMM via mma.sync ========================
// CTA 128(M) x 128(N), K=256 in 8 chunks of 32. 8 warps = 2(M) x 4(N),
// warp tile 64x32. blockIdx.y in [0,6): n0g = y*128; q/k/v = n0g>>8.
__global__ __launch_bounds__(256, 2) void k1_qkv_mma(
    const float* __restrict__ x, const float* __restrict__ bias)
{
    __shared__ __nv_bfloat16 Ah[128][KPAD], Al[128][KPAD];
    __shared__ __nv_bfloat16 Bh[128][KPAD], Bl[128][KPAD];
    __shared__ int boff[128];
    const int tid = threadIdx.x;
    const int wid = tid >> 5, lane = tid & 31;
    const int wm = wid >> 2, wn = wid & 3;
    const int lr = lane >> 2, lc = (lane & 3) * 2;
    const int t0 = blockIdx.x * 128;
    const int n0g = blockIdx.y * 128;

    if (tid < 128) {
        int t = t0 + tid;
        int win = t / 49, n = t - win * 49;
        int b = win >> 8, rem = win & 255;
        boff[tid] = b * (256 * HWD) + ((rem >> 4) * 7 + n / 7) * 112 + (rem & 15) * 7 + n % 7;
    }
    float acc[4][4][4];
    #pragma unroll
    for (int mt = 0; mt < 4; mt++)
        #pragma unroll
        for (int nt = 0; nt < 4; nt++)
            #pragma unroll
            for (int r = 0; r < 4; r++) acc[mt][nt][r] = 0.f;
    __syncthreads();

    for (int cc = 0; cc < 8; cc++) {
        const int kc = cc * 32;
        // A: gather x (7-contiguous w runs), split h/l.
        // 128 m x 16 channel-pairs = 2048 iterations -> i < 8 (2 channels/iter).
        #pragma unroll
        for (int i = 0; i < 8; i++) {
            int idx = tid + i * 256;            // 0..2047
            int m = idx & 127, kp = idx >> 7;   // kp 0..15 -> channels kc+2kp,+1
            const float* px = x + (size_t)boff[m] + (size_t)(kc + 2 * kp) * HWD;
            float v0 = __ldg(px), v1 = __ldg(px + HWD);
            __nv_bfloat162 hh, ll;
            split_bf16(v0, hh.x, ll.x);
            split_bf16(v1, hh.y, ll.y);
            *(__nv_bfloat162*)&Ah[m][2 * kp] = hh;
            *(__nv_bfloat162*)&Al[m][2 * kp] = ll;
        }
        // B: pre-split transposed weights [n][k], coalesced bf162 loads
        #pragma unroll
        for (int i = 0; i < 8; i++) {
            int idx = tid + i * 256;            // 0..2047
            int n = idx >> 4, kp = idx & 15;
            int gi = (n0g + n) * 128 + (kc >> 1) + kp;
            *(__nv_bfloat162*)&Bh[n][2 * kp] = ((const __nv_bfloat162*)g_wqkvT_h)[gi];
            *(__nv_bfloat162*)&Bl[n][2 * kp] = ((const __nv_bfloat162*)g_wqkvT_l)[gi];
        }
        __syncthreads();

        #pragma unroll
        for (int ks = 0; ks < 2; ks++) {
            const int kb = ks * 16;
            uint32_t bh[4][2], bl[4][2];
            #pragma unroll
            for (int nt = 0; nt < 4; nt++) {
                int row = wn * 32 + nt * 8 + lr;
                bh[nt][0] = *(const uint32_t*)&Bh[row][kb + lc];
                bh[nt][1] = *(const uint32_t*)&Bh[row][kb + lc + 8];
                bl[nt][0] = *(const uint32_t*)&Bl[row][kb + lc];
                bl[nt][1] = *(const uint32_t*)&Bl[row][kb + lc + 8];
            }
            #pragma unroll
            for (int mt = 0; mt < 4; mt++) {
                int row = wm * 64 + mt * 16 + lr;
                uint32_t ah[4], al[4];
                ah[0] = *(const uint32_t*)&Ah[row][kb + lc];
                ah[1] = *(const uint32_t*)&Ah[row + 8][kb + lc];
                ah[2] = *(const uint32_t*)&Ah[row][kb + lc + 8];
                ah[3] = *(const uint32_t*)&Ah[row + 8][kb + lc + 8];
                al[0] = *(const uint32_t*)&Al[row][kb + lc];
                al[1] = *(const uint32_t*)&Al[row + 8][kb + lc];
                al[2] = *(const uint32_t*)&Al[row][kb + lc + 8];
                al[3] = *(const uint32_t*)&Al[row + 8][kb + lc + 8];
                #pragma unroll
                for (int nt = 0; nt < 4; nt++) {
                    mma16816(acc[mt][nt], ah, bh[nt]);
                    mma16816(acc[mt][nt], ah, bl[nt]);
                    mma16816(acc[mt][nt], al, bh[nt]);
                }
            }
        }
        __syncthreads();
    }

    // Epilogue: warp's 32-col slice is exactly one head of one of q/k/v.
    {
        int col0 = n0g + wn * 32;
        int which = col0 >> 8;
        int head = (col0 >> 5) & 7;
        float scl = (which == 0) ? QSCALE : 1.f;
        float* dst = (which == 0) ? g_q : (which == 1) ? g_k : g_v;
        #pragma unroll
        for (int nt = 0; nt < 4; nt++) {
            int dloc = nt * 8 + lc;
            float bb0 = __ldg(&bias[col0 + dloc]);
            float bb1 = __ldg(&bias[col0 + dloc + 1]);
            #pragma unroll
            for (int mt = 0; mt < 4; mt++) {
                #pragma unroll
                for (int hf = 0; hf < 2; hf++) {
                    int t = t0 + wm * 64 + mt * 16 + lr + hf * 8;
                    int win = t / 49, n = t - win * 49;
                    size_t off = ((size_t)(win * 8 + head) * 49 + n) * 32 + dloc;
                    float2 v;
                    v.x = (acc[mt][nt][hf * 2 + 0] + bb0) * scl;
                    v.y = (acc[mt][nt][hf * 2 + 1] + bb1) * scl;
                    *(float2*)&dst[off] = v;
                }
            }
        }
    }
}

// ========================= k2: per-(window,head) attention (fp32) ===========
__global__ __launch_bounds__(256) void k2_attn(const float* __restrict__ rpb)
{
    __shared__ float qs[32][56];
    __shared__ float ks[32][56];
    __shared__ float vs[49][33];
    __shared__ float Ss[56][51];
    const int tid  = threadIdx.x;
    const int wh   = blockIdx.x;
    const int head = wh & 7;
    const int win  = wh >> 3;
    const size_t base = (size_t)wh * 1568;

    for (int idx = tid; idx < 1568; idx += 256) {
        int n = idx >> 5, d = idx & 31;
        qs[d][n] = g_q[base + idx];
        ks[d][n] = g_k[base + idx];
        vs[n][d] = g_v[base + idx];
    }
    __syncthreads();

    if (tid < 196) {
        int tyy = tid / 14, txx = tid - tyy * 14;
        int nb = tyy * 4, mb = txx * 4;
        float s[4][4];
        #pragma unroll
        for (int i = 0; i < 4; i++)
            #pragma unroll
            for (int j = 0; j < 4; j++) s[i][j] = 0.f;
        #pragma unroll
        for (int kk = 0; kk < 32; kk++) {
            float qq[4], kf[4];
            #pragma unroll
            for (int i = 0; i < 4; i++) qq[i] = qs[kk][nb + i];
            #pragma unroll
            for (int j = 0; j < 4; j++) kf[j] = ks[kk][mb + j];
            #pragma unroll
            for (int i = 0; i < 4; i++)
                #pragma unroll
                for (int j = 0; j < 4; j++) s[i][j] += qq[i] * kf[j];
        }
        #pragma unroll
        for (int i = 0; i < 4; i++) {
            int n = nb + i;
            if (n < 49) {
                int in_ = n / 7, jn = n - in_ * 7;
                #pragma unroll
                for (int j = 0; j < 4; j++) {
                    int m = mb + j;
                    if (m < 49) {
                        int im = m / 7, jm = m - im * 7;
                        int ridx = (in_ - im + 6) * 13 + (jn - jm + 6);
                        Ss[n][m] = s[i][j] + rpb[ridx * 8 + head];
                    }
                }
            }
        }
    }
    __syncthreads();

    {
        int lane = tid & 31, wrp = tid >> 5;
        for (int r = wrp; r < 49; r += 8) {
            float v0 = Ss[r][lane];
            float v1 = (lane < 17) ? Ss[r][lane + 32] : -3.0e38f;
            float mx = fmaxf(v0, v1);
            #pragma unroll
            for (int o = 16; o; o >>= 1)
                mx = fmaxf(mx, __shfl_xor_sync(0xffffffffu, mx, o));
            float e0 = __expf(v0 - mx);
            float e1 = (lane < 17) ? __expf(v1 - mx) : 0.f;
            float sm = e0 + e1;
            #pragma unroll
            for (int o = 16; o; o >>= 1)
                sm += __shfl_xor_sync(0xffffffffu, sm, o);
            float inv = __fdividef(1.f, sm);
            Ss[r][lane] = e0 * inv;
            if (lane < 17) Ss[r][lane + 32] = e1 * inv;
        }
    }
    __syncthreads();

    float* Os = &qs[0][0];          // stride 53, fits in qs region
    if (tid < 224) {
        int tyy = tid >> 4, txx = tid & 15;
        int nb = tyy * 4, db = txx * 2;
        float o[4][2];
        #pragma unroll
        for (int i = 0; i < 4; i++) { o[i][0] = 0.f; o[i][1] = 0.f; }
        for (int m = 0; m < 49; m++) {
            float va = vs[m][db], vb = vs[m][db + 1];
            #pragma unroll
            for (int i = 0; i < 4; i++) {
                float p = Ss[nb + i][m];
                o[i][0] += p * va;
                o[i][1] += p * vb;
            }
        }
        #pragma unroll
        for (int j = 0; j < 2; j++)
            #pragma unroll
            for (int i = 0; i < 4; i++)
                if (nb + i < 49) Os[(db + j) * 53 + nb + i] = o[i][j];
    }
    __syncthreads();

    for (int e = tid; e < 1568; e += 256) {
        int d = e / 49, n2 = e - d * 49;
        float v = Os[d * 53 + n2];
        __nv_bfloat162 p;
        split_bf16(v, p.x, p.y);
        g_at_hl[(size_t)(head * 32 + d) * TOKS + win * 49 + n2] = p;
    }
}

// ========================= k3: projection GEMM via mma.sync =================
// CTA 128(M) x 128(N), K=256 in 8 chunks. Scatter to NCHW output.
__global__ __launch_bounds__(256, 2) void k3_proj_mma(
    const float* __restrict__ bias, float* __restrict__ out)
{
    __shared__ __nv_bfloat16 Ah[128][KPAD], Al[128][KPAD];
    __shared__ __nv_bfloat16 Bh[128][KPAD], Bl[128][KPAD];
    __shared__ int boff[128];
    const int tid = threadIdx.x;
    const int wid = tid >> 5, lane = tid & 31;
    const int wm = wid >> 2, wn = wid & 3;
    const int lr = lane >> 2, lc = (lane & 3) * 2;
    const int t0 = blockIdx.x * 128;
    const int n0g = blockIdx.y * 128;

    if (tid < 128) {
        int t = t0 + tid;
        int win = t / 49, n = t - win * 49;
        int b = win >> 8, rem = win & 255;
        boff[tid] = b * (256 * HWD) + ((rem >> 4) * 7 + n / 7) * 112 + (rem & 15) * 7 + n % 7;
    }
    float acc[4][4][4];
    #pragma unroll
    for (int mt = 0; mt < 4; mt++)
        #pragma unroll
        for (int nt = 0; nt < 4; nt++)
            #pragma unroll
            for (int r = 0; r < 4; r++) acc[mt][nt][r] = 0.f;
    __syncthreads();

    for (int cc = 0; cc < 8; cc++) {
        const int kc = cc * 32;
        // A: packed (h,l) pairs, ONE element per iteration -> 4096 iters = i<16
        #pragma unroll
        for (int i = 0; i < 16; i++) {
            int idx = tid + i * 256;            // 0..4095
            int m = idx & 127, kk = idx >> 7;   // kk 0..31
            __nv_bfloat162 hl = g_at_hl[(size_t)(kc + kk) * TOKS + t0 + m];
            Ah[m][kk] = hl.x;
            Al[m][kk] = hl.y;
        }
        #pragma unroll
        for (int i = 0; i < 8; i++) {
            int idx = tid + i * 256;            // 0..2047
            int n = idx >> 4, kp = idx & 15;
            int gi = (n0g + n) * 128 + (kc >> 1) + kp;
            *(__nv_bfloat162*)&Bh[n][2 * kp] = ((const __nv_bfloat162*)g_wprojT_h)[gi];
            *(__nv_bfloat162*)&Bl[n][2 * kp] = ((const __nv_bfloat162*)g_wprojT_l)[gi];
        }
        __syncthreads();

        #pragma unroll
        for (int ks = 0; ks < 2; ks++) {
            const int kb = ks * 16;
            uint32_t bh[4][2], bl[4][2];
            #pragma unroll
            for (int nt = 0; nt < 4; nt++) {
                int row = wn * 32 + nt * 8 + lr;
                bh[nt][0] = *(const uint32_t*)&Bh[row][kb + lc];
                bh[nt][1] = *(const uint32_t*)&Bh[row][kb + lc + 8];
                bl[nt][0] = *(const uint32_t*)&Bl[row][kb + lc];
                bl[nt][1] = *(const uint32_t*)&Bl[row][kb + lc + 8];
            }
            #pragma unroll
            for (int mt = 0; mt < 4; mt++) {
                int row = wm * 64 + mt * 16 + lr;
                uint32_t ah[4], al[4];
                ah[0] = *(const uint32_t*)&Ah[row][kb + lc];
                ah[1] = *(const uint32_t*)&Ah[row + 8][kb + lc];
                ah[2] = *(const uint32_t*)&Ah[row][kb + lc + 8];
                ah[3] = *(const uint32_t*)&Ah[row + 8][kb + lc + 8];
                al[0] = *(const uint32_t*)&Al[row][kb + lc];
                al[1] = *(const uint32_t*)&Al[row + 8][kb + lc];
                al[2] = *(const uint32_t*)&Al[row][kb + lc + 8];
                al[3] = *(const uint32_t*)&Al[row + 8][kb + lc + 8];
                #pragma unroll
                for (int nt = 0; nt < 4; nt++) {
                    mma16816(acc[mt][nt], ah, bh[nt]);
                    mma16816(acc[mt][nt], ah, bl[nt]);
                    mma16816(acc[mt][nt], al, bh[nt]);
                }
            }
        }
        __syncthreads();
    }

    // Epilogue: cols = output channels, rows = tokens -> NCHW scatter.
    #pragma unroll
    for (int nt = 0; nt < 4; nt++) {
        int c = n0g + wn * 32 + nt * 8 + lc;
        float bb0 = __ldg(&bias[c]);
        float bb1 = __ldg(&bias[c + 1]);
        #pragma unroll
        for (int mt = 0; mt < 4; mt++) {
            #pragma unroll
            for (int hf = 0; hf < 2; hf++) {
                int bo = boff[wm * 64 + mt * 16 + lr + hf * 8];
                out[bo + (size_t)c * HWD]       = acc[mt][nt][hf * 2 + 0] + bb0;
                out[bo + (size_t)(c + 1) * HWD] = acc[mt][nt][hf * 2 + 1] + bb1;
            }
        }
    }
}

// ---------------------------------------------------------------------------
extern "C" void kernel_launch(void* const* d_in, const int* in_sizes, int n_in,
                              void* d_out, int out_size)
{
    const float* x      = (const float*)d_in[0];
    const float* w_qkv  = (const float*)d_in[1];
    const float* b_qkv  = (const float*)d_in[2];
    const float* w_proj = (const float*)d_in[3];
    const float* b_proj = (const float*)d_in[4];
    const float* rpb    = (const float*)d_in[5];
    float* out = (float*)d_out;

    k0_wqkv<<<768, 256>>>(w_qkv);
    k0_wproj<<<256, 256>>>(w_proj);
    k1_qkv_mma<<<dim3(784, 6), 256>>>(x, b_qkv);
    k2_attn<<<16384, 256>>>(rpb);
    k3_proj_mma<<<dim3(784, 2), 256>>>(b_proj, out);
}

// round 10
// speedup vs baseline: 3.5254x; 1.4465x over previous
#include <cuda_runtime.h>
#include <cuda_bf16.h>
#include <cstdint>

#define HWD 12544        // 112*112
#define TOKS 100352      // 2048 windows * 49
#define QSCALE 0.17677669529663687f   // 32^-0.5

// ========================= device scratch ===================================
__device__ float g_q[(size_t)TOKS * 256];
__device__ float g_k[(size_t)TOKS * 256];
__device__ float g_v[(size_t)TOKS * 256];
__device__ __nv_bfloat16 g_xh[(size_t)TOKS * 256];   // x gathered [t][c], high
__device__ __nv_bfloat16 g_xl[(size_t)TOKS * 256];   // low
__device__ __nv_bfloat16 g_ath[(size_t)TOKS * 256];  // attn out [t][c], high
__device__ __nv_bfloat16 g_atl[(size_t)TOKS * 256];  // low
__device__ __nv_bfloat16 g_wqkvT_h[768 * 256];       // [n][k]
__device__ __nv_bfloat16 g_wqkvT_l[768 * 256];
__device__ __nv_bfloat16 g_wprojT_h[256 * 256];
__device__ __nv_bfloat16 g_wprojT_l[256 * 256];

__device__ __forceinline__ void split_bf16(float v, __nv_bfloat16& h, __nv_bfloat16& l) {
    h = __float2bfloat16(v);
    l = __float2bfloat16(v - __bfloat162float(h));
}

// mma.sync m16n8k16 bf16 (base ISA, sm_80+)
__device__ __forceinline__ void mma16816(
    float* d, const uint32_t* a, const uint32_t* b)
{
    asm volatile(
        "mma.sync.aligned.m16n8k16.row.col.f32.bf16.bf16.f32 "
        "{%0,%1,%2,%3}, {%4,%5,%6,%7}, {%8,%9}, {%0,%1,%2,%3};"
        : "+f"(d[0]), "+f"(d[1]), "+f"(d[2]), "+f"(d[3])
        : "r"(a[0]), "r"(a[1]), "r"(a[2]), "r"(a[3]), "r"(b[0]), "r"(b[1]));
}

__device__ __forceinline__ void cp16(void* dst, const void* src) {
    uint32_t d = (uint32_t)__cvta_generic_to_shared(dst);
    asm volatile("cp.async.ca.shared.global [%0], [%1], 16;" :: "r"(d), "l"(src));
}
#define CP_COMMIT() asm volatile("cp.async.commit_group;" ::: "memory")
#define CP_WAIT1()  asm volatile("cp.async.wait_group 1;" ::: "memory")
#define CP_WAIT0()  asm volatile("cp.async.wait_group 0;" ::: "memory")

#define KPAD 40            // bf16 per smem row (32 data + 8 pad); 80B stride
#define PL (128 * KPAD)    // plane elems
#define SMEM_DYN (2 * 4 * PL * 2)   // 2 bufs x 4 planes x PL bf16 = 81920 B

// ========================= k0: weight transpose + split =====================
__global__ void k0_wqkv(const float* __restrict__ w) {
    int idx = blockIdx.x * 256 + threadIdx.x;
    int k = idx / 768, n = idx % 768;
    __nv_bfloat16 h, l; split_bf16(w[idx], h, l);
    g_wqkvT_h[n * 256 + k] = h;
    g_wqkvT_l[n * 256 + k] = l;
}
__global__ void k0_wproj(const float* __restrict__ w) {
    int idx = blockIdx.x * 256 + threadIdx.x;
    int k = idx >> 8, n = idx & 255;
    __nv_bfloat16 h, l; split_bf16(w[idx], h, l);
    g_wprojT_h[n * 256 + k] = h;
    g_wprojT_l[n * 256 + k] = l;
}

// ========================= k0x: gather + split x -> [t][c] h/l planes =======
__global__ __launch_bounds__(256) void k0x(const float* __restrict__ x)
{
    __shared__ __nv_bfloat16 sh[32 * 266], sl[32 * 266];
    __shared__ int boff[32];
    const int tid = threadIdx.x;
    const int t0 = blockIdx.x * 32;
    if (tid < 32) {
        int t = t0 + tid;
        int win = t / 49, n = t - win * 49;
        int b = win >> 8, rem = win & 255;
        boff[tid] = b * (256 * HWD) + ((rem >> 4) * 7 + n / 7) * 112 + (rem & 15) * 7 + n % 7;
    }
    __syncthreads();
    {
        int t = tid & 31, c0 = tid >> 5;
        int bo = boff[t];
        #pragma unroll
        for (int it = 0; it < 32; it++) {
            int c = c0 + it * 8;
            float v = __ldg(&x[(size_t)bo + (size_t)c * HWD]);
            __nv_bfloat16 h, l; split_bf16(v, h, l);
            sh[t * 266 + c] = h;
            sl[t * 266 + c] = l;
        }
    }
    __syncthreads();
    #pragma unroll
    for (int i = 0; i < 16; i++) {
        int idx = tid + i * 256;            // 0..4095
        int tt = idx >> 7, cp2 = idx & 127; // channel pair
        uint32_t hv = *(uint32_t*)&sh[tt * 266 + cp2 * 2];
        uint32_t lv = *(uint32_t*)&sl[tt * 266 + cp2 * 2];
        *(uint32_t*)&g_xh[(size_t)(t0 + tt) * 256 + cp2 * 2] = hv;
        *(uint32_t*)&g_xl[(size_t)(t0 + tt) * 256 + cp2 * 2] = lv;
    }
}

// ========================= k1: QKV GEMM, cp.async double-buffered ===========
// CTA 128(M) x 128(N), K=256 in 8 chunks of 32. 8 warps = 2(M) x 4(N).
__device__ __forceinline__ void k1_load_chunk(
    __nv_bfloat16* dsm, int buf, int cc, int tid, int t0, int n0g)
{
    const int kc = cc * 32;
    __nv_bfloat16* bb = dsm + buf * 4 * PL;
    #pragma unroll
    for (int i = 0; i < 4; i++) {
        int idx = tid + i * 256;            // A: 0..1023
        int m = idx >> 3, sub = idx & 7, pl = sub >> 2, c4 = sub & 3;
        const __nv_bfloat16* src = (pl ? g_xl : g_xh) + (size_t)(t0 + m) * 256 + kc + c4 * 8;
        cp16(bb + pl * PL + m * KPAD + c4 * 8, src);
    }
    #pragma unroll
    for (int i = 0; i < 4; i++) {
        int idx = tid + i * 256;            // B: 0..1023
        int n = idx >> 3, sub = idx & 7, pl = sub >> 2, c4 = sub & 3;
        const __nv_bfloat16* src = (pl ? g_wqkvT_l : g_wqkvT_h) + (size_t)(n0g + n) * 256 + kc + c4 * 8;
        cp16(bb + (2 + pl) * PL + n * KPAD + c4 * 8, src);
    }
    CP_COMMIT();
}

__global__ __launch_bounds__(256, 2) void k1_qkv_mma(const float* __restrict__ bias)
{
    extern __shared__ __nv_bfloat16 dsm[];
    const int tid = threadIdx.x;
    const int wid = tid >> 5, lane = tid & 31;
    const int wm = wid >> 2, wn = wid & 3;
    const int lr = lane >> 2, lc = (lane & 3) * 2;
    const int t0 = blockIdx.x * 128;
    const int n0g = blockIdx.y * 128;

    float acc[4][4][4];
    #pragma unroll
    for (int mt = 0; mt < 4; mt++)
        #pragma unroll
        for (int nt = 0; nt < 4; nt++)
            #pragma unroll
            for (int r = 0; r < 4; r++) acc[mt][nt][r] = 0.f;

    k1_load_chunk(dsm, 0, 0, tid, t0, n0g);
    for (int cc = 0; cc < 8; cc++) {
        if (cc < 7) { k1_load_chunk(dsm, (cc + 1) & 1, cc + 1, tid, t0, n0g); CP_WAIT1(); }
        else CP_WAIT0();
        __syncthreads();
        const __nv_bfloat16* bb = dsm + (cc & 1) * 4 * PL;
        const __nv_bfloat16* Ah = bb;
        const __nv_bfloat16* Al = bb + PL;
        const __nv_bfloat16* Bh = bb + 2 * PL;
        const __nv_bfloat16* Bl = bb + 3 * PL;
        #pragma unroll
        for (int ks = 0; ks < 2; ks++) {
            const int kb = ks * 16;
            uint32_t bh[4][2], bl[4][2];
            #pragma unroll
            for (int nt = 0; nt < 4; nt++) {
                int row = wn * 32 + nt * 8 + lr;
                bh[nt][0] = *(const uint32_t*)&Bh[row * KPAD + kb + lc];
                bh[nt][1] = *(const uint32_t*)&Bh[row * KPAD + kb + lc + 8];
                bl[nt][0] = *(const uint32_t*)&Bl[row * KPAD + kb + lc];
                bl[nt][1] = *(const uint32_t*)&Bl[row * KPAD + kb + lc + 8];
            }
            #pragma unroll
            for (int mt = 0; mt < 4; mt++) {
                int row = wm * 64 + mt * 16 + lr;
                uint32_t ah[4], al[4];
                ah[0] = *(const uint32_t*)&Ah[row * KPAD + kb + lc];
                ah[1] = *(const uint32_t*)&Ah[(row + 8) * KPAD + kb + lc];
                ah[2] = *(const uint32_t*)&Ah[row * KPAD + kb + lc + 8];
                ah[3] = *(const uint32_t*)&Ah[(row + 8) * KPAD + kb + lc + 8];
                al[0] = *(const uint32_t*)&Al[row * KPAD + kb + lc];
                al[1] = *(const uint32_t*)&Al[(row + 8) * KPAD + kb + lc];
                al[2] = *(const uint32_t*)&Al[row * KPAD + kb + lc + 8];
                al[3] = *(const uint32_t*)&Al[(row + 8) * KPAD + kb + lc + 8];
                #pragma unroll
                for (int nt = 0; nt < 4; nt++) {
                    mma16816(acc[mt][nt], ah, bh[nt]);
                    mma16816(acc[mt][nt], ah, bl[nt]);
                    mma16816(acc[mt][nt], al, bh[nt]);
                }
            }
        }
        __syncthreads();
    }

    // Epilogue: warp's 32-col slice = one head of one of q/k/v.
    {
        int col0 = n0g + wn * 32;
        int which = col0 >> 8;
        int head = (col0 >> 5) & 7;
        float scl = (which == 0) ? QSCALE : 1.f;
        float* dst = (which == 0) ? g_q : (which == 1) ? g_k : g_v;
        #pragma unroll
        for (int nt = 0; nt < 4; nt++) {
            int dloc = nt * 8 + lc;
            float bb0 = __ldg(&bias[col0 + dloc]);
            float bb1 = __ldg(&bias[col0 + dloc + 1]);
            #pragma unroll
            for (int mt = 0; mt < 4; mt++) {
                #pragma unroll
                for (int hf = 0; hf < 2; hf++) {
                    int t = t0 + wm * 64 + mt * 16 + lr + hf * 8;
                    int win = t / 49, n = t - win * 49;
                    size_t off = ((size_t)(win * 8 + head) * 49 + n) * 32 + dloc;
                    float2 v;
                    v.x = (acc[mt][nt][hf * 2 + 0] + bb0) * scl;
                    v.y = (acc[mt][nt][hf * 2 + 1] + bb1) * scl;
                    *(float2*)&dst[off] = v;
                }
            }
        }
    }
}

// ========================= k2: per-(window,head) attention (fp32) ===========
__global__ __launch_bounds__(256) void k2_attn(const float* __restrict__ rpb)
{
    __shared__ float bufA[3584];        // qs[d][n]@56 | ks at +1792 ; later PT[m][n]@52
    __shared__ float vs[49][34];
    __shared__ float Ss[56][51];        // scores; later Os[d][n]@53
    const int tid  = threadIdx.x;
    const int wh   = blockIdx.x;
    const int head = wh & 7;
    const int win  = wh >> 3;
    const size_t base = (size_t)wh * 1568;
    float* qsp = bufA;
    float* ksp = bufA + 1792;

    for (int idx = tid; idx < 1568; idx += 256) {
        int n = idx >> 5, d = idx & 31;
        qsp[d * 56 + n] = g_q[base + idx];
        ksp[d * 56 + n] = g_k[base + idx];
        vs[n][d] = g_v[base + idx];
    }
    __syncthreads();

    // ---- scores: 196 threads, 4x4 tiles, float4 fragment loads ----
    if (tid < 196) {
        int tyy = tid / 14, txx = tid - tyy * 14;
        int nb = tyy * 4, mb = txx * 4;
        float s[4][4];
        #pragma unroll
        for (int i = 0; i < 4; i++)
            #pragma unroll
            for (int j = 0; j < 4; j++) s[i][j] = 0.f;
        #pragma unroll
        for (int kk = 0; kk < 32; kk++) {
            float4 qq = *(const float4*)(qsp + kk * 56 + nb);
            float4 kf = *(const float4*)(ksp + kk * 56 + mb);
            const float* qa = &qq.x;
            const float* ka = &kf.x;
            #pragma unroll
            for (int i = 0; i < 4; i++)
                #pragma unroll
                for (int j = 0; j < 4; j++) s[i][j] += qa[i] * ka[j];
        }
        #pragma unroll
        for (int i = 0; i < 4; i++) {
            int n = nb + i;
            if (n < 49) {
                int in_ = n / 7, jn = n - in_ * 7;
                #pragma unroll
                for (int j = 0; j < 4; j++) {
                    int m = mb + j;
                    if (m < 49) {
                        int im = m / 7, jm = m - im * 7;
                        int ridx = (in_ - im + 6) * 13 + (jn - jm + 6);
                        Ss[n][m] = s[i][j] + rpb[ridx * 8 + head];
                    }
                }
            }
        }
    }
    __syncthreads();

    // ---- softmax: warp per row; write P TRANSPOSED into bufA (PT[m][n]@52)
    {
        int lane = tid & 31, wrp = tid >> 5;
        for (int r = wrp; r < 49; r += 8) {
            float v0 = Ss[r][lane];
            float v1 = (lane < 17) ? Ss[r][lane + 32] : -3.0e38f;
            float mx = fmaxf(v0, v1);
            #pragma unroll
            for (int o = 16; o; o >>= 1)
                mx = fmaxf(mx, __shfl_xor_sync(0xffffffffu, mx, o));
            float e0 = __expf(v0 - mx);
            float e1 = (lane < 17) ? __expf(v1 - mx) : 0.f;
            float sm = e0 + e1;
            #pragma unroll
            for (int o = 16; o; o >>= 1)
                sm += __shfl_xor_sync(0xffffffffu, sm, o);
            float inv = __fdividef(1.f, sm);
            bufA[lane * 52 + r] = e0 * inv;
            if (lane < 17) bufA[(lane + 32) * 52 + r] = e1 * inv;
        }
    }
    __syncthreads();

    // ---- O = P@V : 224 threads, 4(n) x 2(d); PT row loads are float4 ----
    float o[4][2];
    int nb2 = 0, db2 = 0;
    if (tid < 224) {
        int tyy = tid >> 4, txx = tid & 15;
        nb2 = tyy * 4; db2 = txx * 2;
        #pragma unroll
        for (int i = 0; i < 4; i++) { o[i][0] = 0.f; o[i][1] = 0.f; }
        for (int m = 0; m < 49; m++) {
            float4 p = *(const float4*)(bufA + m * 52 + nb2);
            float2 vv = *(const float2*)(&vs[m][db2]);
            const float* pa = &p.x;
            #pragma unroll
            for (int i = 0; i < 4; i++) {
                o[i][0] += pa[i] * vv.x;
                o[i][1] += pa[i] * vv.y;
            }
        }
    }
    __syncthreads();                     // PT reads done before Os overlays... (Os is in Ss, distinct) 
    float* Os = &Ss[0][0];               // stride 53; 31*53+48=1691 < 2856
    if (tid < 224) {
        #pragma unroll
        for (int j = 0; j < 2; j++)
            #pragma unroll
            for (int i = 0; i < 4; i++)
                if (nb2 + i < 49) Os[(db2 + j) * 53 + nb2 + i] = o[i][j];
    }
    __syncthreads();

    // final: write [t][c] h/l planes, c fast -> coalesced
    for (int e = tid; e < 1568; e += 256) {
        int nloc = e >> 5, d = e & 31;
        float v = Os[d * 53 + nloc];
        __nv_bfloat16 h, l; split_bf16(v, h, l);
        size_t gi = (size_t)(win * 49 + nloc) * 256 + head * 32 + d;
        g_ath[gi] = h;
        g_atl[gi] = l;
    }
}

// ========================= k3: projection GEMM, cp.async ====================
__device__ __forceinline__ void k3_load_chunk(
    __nv_bfloat16* dsm, int buf, int cc, int tid, int t0, int n0g)
{
    const int kc = cc * 32;
    __nv_bfloat16* bb = dsm + buf * 4 * PL;
    #pragma unroll
    for (int i = 0; i < 4; i++) {
        int idx = tid + i * 256;
        int m = idx >> 3, sub = idx & 7, pl = sub >> 2, c4 = sub & 3;
        const __nv_bfloat16* src = (pl ? g_atl : g_ath) + (size_t)(t0 + m) * 256 + kc + c4 * 8;
        cp16(bb + pl * PL + m * KPAD + c4 * 8, src);
    }
    #pragma unroll
    for (int i = 0; i < 4; i++) {
        int idx = tid + i * 256;
        int n = idx >> 3, sub = idx & 7, pl = sub >> 2, c4 = sub & 3;
        const __nv_bfloat16* src = (pl ? g_wprojT_l : g_wprojT_h) + (size_t)(n0g + n) * 256 + kc + c4 * 8;
        cp16(bb + (2 + pl) * PL + n * KPAD + c4 * 8, src);
    }
    CP_COMMIT();
}

__global__ __launch_bounds__(256, 2) void k3_proj_mma(
    const float* __restrict__ bias, float* __restrict__ out)
{
    extern __shared__ __nv_bfloat16 dsm[];
    __shared__ int boff[128];
    const int tid = threadIdx.x;
    const int wid = tid >> 5, lane = tid & 31;
    const int wm = wid >> 2, wn = wid & 3;
    const int lr = lane >> 2, lc = (lane & 3) * 2;
    const int t0 = blockIdx.x * 128;
    const int n0g = blockIdx.y * 128;

    if (tid < 128) {
        int t = t0 + tid;
        int win = t / 49, n = t - win * 49;
        int b = win >> 8, rem = win & 255;
        boff[tid] = b * (256 * HWD) + ((rem >> 4) * 7 + n / 7) * 112 + (rem & 15) * 7 + n % 7;
    }
    float acc[4][4][4];
    #pragma unroll
    for (int mt = 0; mt < 4; mt++)
        #pragma unroll
        for (int nt = 0; nt < 4; nt++)
            #pragma unroll
            for (int r = 0; r < 4; r++) acc[mt][nt][r] = 0.f;

    k3_load_chunk(dsm, 0, 0, tid, t0, n0g);
    for (int cc = 0; cc < 8; cc++) {
        if (cc < 7) { k3_load_chunk(dsm, (cc + 1) & 1, cc + 1, tid, t0, n0g); CP_WAIT1(); }
        else CP_WAIT0();
        __syncthreads();
        const __nv_bfloat16* bb = dsm + (cc & 1) * 4 * PL;
        const __nv_bfloat16* Ah = bb;
        const __nv_bfloat16* Al = bb + PL;
        const __nv_bfloat16* Bh = bb + 2 * PL;
        const __nv_bfloat16* Bl = bb + 3 * PL;
        #pragma unroll
        for (int ks = 0; ks < 2; ks++) {
            const int kb = ks * 16;
            uint32_t bh[4][2], bl[4][2];
            #pragma unroll
            for (int nt = 0; nt < 4; nt++) {
                int row = wn * 32 + nt * 8 + lr;
                bh[nt][0] = *(const uint32_t*)&Bh[row * KPAD + kb + lc];
                bh[nt][1] = *(const uint32_t*)&Bh[row * KPAD + kb + lc + 8];
                bl[nt][0] = *(const uint32_t*)&Bl[row * KPAD + kb + lc];
                bl[nt][1] = *(const uint32_t*)&Bl[row * KPAD + kb + lc + 8];
            }
            #pragma unroll
            for (int mt = 0; mt < 4; mt++) {
                int row = wm * 64 + mt * 16 + lr;
                uint32_t ah[4], al[4];
                ah[0] = *(const uint32_t*)&Ah[row * KPAD + kb + lc];
                ah[1] = *(const uint32_t*)&Ah[(row + 8) * KPAD + kb + lc];
                ah[2] = *(const uint32_t*)&Ah[row * KPAD + kb + lc + 8];
                ah[3] = *(const uint32_t*)&Ah[(row + 8) * KPAD + kb + lc + 8];
                al[0] = *(const uint32_t*)&Al[row * KPAD + kb + lc];
                al[1] = *(const uint32_t*)&Al[(row + 8) * KPAD + kb + lc];
                al[2] = *(const uint32_t*)&Al[row * KPAD + kb + lc + 8];
                al[3] = *(const uint32_t*)&Al[(row + 8) * KPAD + kb + lc + 8];
                #pragma unroll
                for (int nt = 0; nt < 4; nt++) {
                    mma16816(acc[mt][nt], ah, bh[nt]);
                    mma16816(acc[mt][nt], ah, bl[nt]);
                    mma16816(acc[mt][nt], al, bh[nt]);
                }
            }
        }
        __syncthreads();
    }

    // Epilogue: NCHW scatter
    #pragma unroll
    for (int nt = 0; nt < 4; nt++) {
        int c = n0g + wn * 32 + nt * 8 + lc;
        float bb0 = __ldg(&bias[c]);
        float bb1 = __ldg(&bias[c + 1]);
        #pragma unroll
        for (int mt = 0; mt < 4; mt++) {
            #pragma unroll
            for (int hf = 0; hf < 2; hf++) {
                int bo = boff[wm * 64 + mt * 16 + lr + hf * 8];
                out[bo + (size_t)c * HWD]       = acc[mt][nt][hf * 2 + 0] + bb0;
                out[bo + (size_t)(c + 1) * HWD] = acc[mt][nt][hf * 2 + 1] + bb1;
            }
        }
    }
}

// ---------------------------------------------------------------------------
extern "C" void kernel_launch(void* const* d_in, const int* in_sizes, int n_in,
                              void* d_out, int out_size)
{
    const float* x      = (const float*)d_in[0];
    const float* w_qkv  = (const float*)d_in[1];
    const float* b_qkv  = (const float*)d_in[2];
    const float* w_proj = (const float*)d_in[3];
    const float* b_proj = (const float*)d_in[4];
    const float* rpb    = (const float*)d_in[5];
    float* out = (float*)d_out;

    cudaFuncSetAttribute(k1_qkv_mma, cudaFuncAttributeMaxDynamicSharedMemorySize, SMEM_DYN);
    cudaFuncSetAttribute(k3_proj_mma, cudaFuncAttributeMaxDynamicSharedMemorySize, SMEM_DYN);

    k0_wqkv<<<768, 256>>>(w_qkv);
    k0_wproj<<<256, 256>>>(w_proj);
    k0x<<<3136, 256>>>(x);
    k1_qkv_mma<<<dim3(784, 6), 256, SMEM_DYN>>>(b_qkv);
    k2_attn<<<16384, 256>>>(rpb);
    k3_proj_mma<<<dim3(784, 2), 256, SMEM_DYN>>>(b_proj, out);
}